// round 5
// baseline (speedup 1.0000x reference)
#include <cuda_runtime.h>

#define BATCH 4096
#define FEAT  4096
#define BLOCKS 512
#define ROWS_PER_CTA (BATCH / BLOCKS)   // 8

// scratch (device-global; no allocation allowed in kernel_launch)
__device__ float g_partial[BLOCKS];
__device__ unsigned int g_done;   // zero at module load; reset by last CTA each run

__global__ void __launch_bounds__(256) myloss_kernel(
    const float* __restrict__ out1,
    const float* __restrict__ out2,
    const float* __restrict__ out3,
    float* __restrict__ out)
{
    const int lane = threadIdx.x & 31;
    const int wid  = threadIdx.x >> 5;

    __shared__ float sh13[2][8];   // parity-buffered per-row reductions
    __shared__ float sh12[2][8];
    __shared__ bool  is_last;

    float hinge_acc = 0.0f;        // only meaningful on thread 0

    #pragma unroll
    for (int r = 0; r < ROWS_PER_CTA; ++r) {
        const int row = blockIdx.x * ROWS_PER_CTA + r;
        const size_t base = (size_t)row * FEAT;
        const float4* __restrict__ p1 = reinterpret_cast<const float4*>(out1 + base);
        const float4* __restrict__ p2 = reinterpret_cast<const float4*>(out2 + base);
        const float4* __restrict__ p3 = reinterpret_cast<const float4*>(out3 + base);

        float s13 = 0.0f;
        float s12 = 0.0f;

        // FEAT/4 = 1024 float4 per row; 256 threads -> 4 iterations each.
        #pragma unroll
        for (int it = 0; it < (FEAT / 4) / 256; ++it) {
            const int i = it * 256 + threadIdx.x;
            float4 a = __ldcs(p1 + i);
            float4 b = __ldcs(p2 + i);
            float4 c = __ldcs(p3 + i);
            float d;
            d = a.x - c.x; s13 = fmaf(d, d, s13);
            d = a.y - c.y; s13 = fmaf(d, d, s13);
            d = a.z - c.z; s13 = fmaf(d, d, s13);
            d = a.w - c.w; s13 = fmaf(d, d, s13);
            d = a.x - b.x; s12 = fmaf(d, d, s12);
            d = a.y - b.y; s12 = fmaf(d, d, s12);
            d = a.z - b.z; s12 = fmaf(d, d, s12);
            d = a.w - b.w; s12 = fmaf(d, d, s12);
        }

        // warp reduction of both sums
        #pragma unroll
        for (int off = 16; off > 0; off >>= 1) {
            s13 += __shfl_xor_sync(0xFFFFFFFFu, s13, off);
            s12 += __shfl_xor_sync(0xFFFFFFFFu, s12, off);
        }

        const int pb = r & 1;
        if (lane == 0) { sh13[pb][wid] = s13; sh12[pb][wid] = s12; }
        __syncthreads();   // single barrier per row (parity buffers avoid WAR)

        if (threadIdx.x == 0) {
            float a13 = 0.0f, a12 = 0.0f;
            #pragma unroll
            for (int w = 0; w < 8; ++w) { a13 += sh13[pb][w]; a12 += sh12[pb][w]; }
            float compare = 2.0f - sqrtf(a13) + sqrtf(a12);
            hinge_acc += fmaxf(0.0f, compare);
        }
    }

    // ---- CTA epilogue: publish partial, last CTA reduces (512 gpu-scope ops total) ----
    if (threadIdx.x == 0) {
        g_partial[blockIdx.x] = hinge_acc;
        __threadfence();
        unsigned int t = atomicAdd(&g_done, 1u);
        is_last = (t == (unsigned int)(BLOCKS - 1));
    }
    __syncthreads();

    if (is_last) {
        // 512 partials, 256 threads -> 2 each (L2-hot)
        float s = g_partial[threadIdx.x] + g_partial[threadIdx.x + 256];

        #pragma unroll
        for (int off = 16; off > 0; off >>= 1)
            s += __shfl_xor_sync(0xFFFFFFFFu, s, off);

        __shared__ float shf[8];
        if (lane == 0) shf[wid] = s;
        __syncthreads();

        if (threadIdx.x == 0) {
            float tot = 0.0f;
            #pragma unroll
            for (int w = 0; w < 8; ++w) tot += shf[w];
            out[0] = tot * (float)BATCH;   // [B,B] broadcast -> scale by B
            g_done = 0;                    // reset for next graph replay
        }
    }
}

extern "C" void kernel_launch(void* const* d_in, const int* in_sizes, int n_in,
                              void* d_out, int out_size)
{
    const float* out1 = (const float*)d_in[0];
    const float* out2 = (const float*)d_in[1];
    const float* out3 = (const float*)d_in[2];
    float* out = (float*)d_out;

    myloss_kernel<<<BLOCKS, 256>>>(out1, out2, out3, out);
}

// round 6
// speedup vs baseline: 1.1159x; 1.1159x over previous
#include <cuda_runtime.h>

#define BATCH 4096
#define FEAT  4096

// scratch (device-global; no allocation allowed in kernel_launch)
__device__ float g_row_hinge[BATCH];
__device__ unsigned int g_done;   // zero at load; reset by reduce kernel each run

__global__ void __launch_bounds__(256) row_dist_kernel(
    const float* __restrict__ out1,
    const float* __restrict__ out2,
    const float* __restrict__ out3)
{
    // Fire the PDL trigger immediately: the dependent reduce kernel may launch
    // once every CTA of this grid has started (start of last wave), and then
    // spin-waits on g_done instead of waiting for full grid completion.
#if __CUDA_ARCH__ >= 900
    cudaTriggerProgrammaticLaunchCompletion();
#endif

    const int row = blockIdx.x;
    const size_t base = (size_t)row * FEAT;
    const float4* __restrict__ p1 = reinterpret_cast<const float4*>(out1 + base);
    const float4* __restrict__ p2 = reinterpret_cast<const float4*>(out2 + base);
    const float4* __restrict__ p3 = reinterpret_cast<const float4*>(out3 + base);

    float s13 = 0.0f;  // sum (o1-o3)^2
    float s12 = 0.0f;  // sum (o1-o2)^2

    // FEAT/4 = 1024 float4 per row; 256 threads -> 4 iterations each.
    #pragma unroll
    for (int it = 0; it < (FEAT / 4) / 256; ++it) {
        const int i = it * 256 + threadIdx.x;
        float4 a = __ldcs(p1 + i);
        float4 b = __ldcs(p2 + i);
        float4 c = __ldcs(p3 + i);
        float d;
        d = a.x - c.x; s13 = fmaf(d, d, s13);
        d = a.y - c.y; s13 = fmaf(d, d, s13);
        d = a.z - c.z; s13 = fmaf(d, d, s13);
        d = a.w - c.w; s13 = fmaf(d, d, s13);
        d = a.x - b.x; s12 = fmaf(d, d, s12);
        d = a.y - b.y; s12 = fmaf(d, d, s12);
        d = a.z - b.z; s12 = fmaf(d, d, s12);
        d = a.w - b.w; s12 = fmaf(d, d, s12);
    }

    // warp reduction of both sums
    #pragma unroll
    for (int off = 16; off > 0; off >>= 1) {
        s13 += __shfl_xor_sync(0xFFFFFFFFu, s13, off);
        s12 += __shfl_xor_sync(0xFFFFFFFFu, s12, off);
    }

    __shared__ float sh13[8];
    __shared__ float sh12[8];
    const int lane = threadIdx.x & 31;
    const int wid  = threadIdx.x >> 5;
    if (lane == 0) { sh13[wid] = s13; sh12[wid] = s12; }
    __syncthreads();

    if (threadIdx.x == 0) {
        float a13 = 0.0f, a12 = 0.0f;
        #pragma unroll
        for (int w = 0; w < 8; ++w) { a13 += sh13[w]; a12 += sh12[w]; }
        float compare = 2.0f - sqrtf(a13) + sqrtf(a12);
        g_row_hinge[row] = fmaxf(0.0f, compare);
        // Publish: release-ordered count makes the hinge store visible to any
        // acquire reader of g_done. Fire-and-forget (no return, no membar).
        asm volatile("red.release.gpu.global.add.u32 [%0], 1;"
                     :: "l"(&g_done) : "memory");
    }
}

__global__ void __launch_bounds__(1024) final_reduce_kernel(float* __restrict__ out)
{
    // Spin until all 4096 CTAs of the primary have published their hinge.
    if (threadIdx.x == 0) {
        unsigned int v;
        do {
            asm volatile("ld.acquire.gpu.global.u32 %0, [%1];"
                         : "=r"(v) : "l"(&g_done) : "memory");
        } while (v < (unsigned int)BATCH);
    }
    __syncthreads();   // block fence: extends thread0's acquire to the CTA

    // 1024 threads x 1 float4 = 4096 floats (L2-hot).
    const float4 v4 = reinterpret_cast<const float4*>(g_row_hinge)[threadIdx.x];
    float s = (v4.x + v4.y) + (v4.z + v4.w);

    #pragma unroll
    for (int off = 16; off > 0; off >>= 1)
        s += __shfl_xor_sync(0xFFFFFFFFu, s, off);

    __shared__ float sh[32];
    const int lane = threadIdx.x & 31;
    const int wid  = threadIdx.x >> 5;
    if (lane == 0) sh[wid] = s;
    __syncthreads();

    if (wid == 0) {
        s = sh[lane];
        #pragma unroll
        for (int off = 16; off > 0; off >>= 1)
            s += __shfl_xor_sync(0xFFFFFFFFu, s, off);
        if (lane == 0) {
            out[0] = s * (float)BATCH;  // [B,B] broadcast -> scale by B
            g_done = 0;                 // reset for the next launch/replay
        }
    }
}

extern "C" void kernel_launch(void* const* d_in, const int* in_sizes, int n_in,
                              void* d_out, int out_size)
{
    const float* out1 = (const float*)d_in[0];
    const float* out2 = (const float*)d_in[1];
    const float* out3 = (const float*)d_in[2];
    float* out = (float*)d_out;

    row_dist_kernel<<<BATCH, 256>>>(out1, out2, out3);

    // Dependent launch: allowed to start once every primary CTA has executed
    // its trigger (start of the last wave). It then spin-waits on g_done,
    // avoiding the slow full-grid completion flush.
    cudaLaunchConfig_t cfg = {};
    cfg.gridDim  = dim3(1, 1, 1);
    cfg.blockDim = dim3(1024, 1, 1);
    cfg.dynamicSmemBytes = 0;
    cfg.stream = 0;

    cudaLaunchAttribute attr[1];
    attr[0].id = cudaLaunchAttributeProgrammaticStreamSerialization;
    attr[0].val.programmaticStreamSerializationAllowed = 1;
    cfg.attrs = attr;
    cfg.numAttrs = 1;

    cudaLaunchKernelEx(&cfg, final_reduce_kernel, out);
}

// round 7
// speedup vs baseline: 1.1170x; 1.0009x over previous
#include <cuda_runtime.h>

#define BATCH 4096
#define FEAT  4096

// scratch (device-global; no allocation allowed in kernel_launch)
__device__ float g_row_hinge[BATCH];
__device__ unsigned int g_done;   // zero at load; reset by designated CTA each run

__global__ void __launch_bounds__(256) myloss_kernel(
    const float* __restrict__ out1,
    const float* __restrict__ out2,
    const float* __restrict__ out3,
    float* __restrict__ out)
{
    const int row = blockIdx.x;
    const size_t base = (size_t)row * FEAT;
    const float4* __restrict__ p1 = reinterpret_cast<const float4*>(out1 + base);
    const float4* __restrict__ p2 = reinterpret_cast<const float4*>(out2 + base);
    const float4* __restrict__ p3 = reinterpret_cast<const float4*>(out3 + base);

    float s13 = 0.0f;  // sum (o1-o3)^2
    float s12 = 0.0f;  // sum (o1-o2)^2

    // FEAT/4 = 1024 float4 per row; 256 threads -> 4 iterations each.
    #pragma unroll
    for (int it = 0; it < (FEAT / 4) / 256; ++it) {
        const int i = it * 256 + threadIdx.x;
        float4 a = __ldcs(p1 + i);
        float4 b = __ldcs(p2 + i);
        float4 c = __ldcs(p3 + i);
        float d;
        d = a.x - c.x; s13 = fmaf(d, d, s13);
        d = a.y - c.y; s13 = fmaf(d, d, s13);
        d = a.z - c.z; s13 = fmaf(d, d, s13);
        d = a.w - c.w; s13 = fmaf(d, d, s13);
        d = a.x - b.x; s12 = fmaf(d, d, s12);
        d = a.y - b.y; s12 = fmaf(d, d, s12);
        d = a.z - b.z; s12 = fmaf(d, d, s12);
        d = a.w - b.w; s12 = fmaf(d, d, s12);
    }

    // warp reduction of both sums
    #pragma unroll
    for (int off = 16; off > 0; off >>= 1) {
        s13 += __shfl_xor_sync(0xFFFFFFFFu, s13, off);
        s12 += __shfl_xor_sync(0xFFFFFFFFu, s12, off);
    }

    __shared__ float sh13[8];
    __shared__ float sh12[8];
    const int lane = threadIdx.x & 31;
    const int wid  = threadIdx.x >> 5;
    if (lane == 0) { sh13[wid] = s13; sh12[wid] = s12; }
    __syncthreads();

    if (threadIdx.x == 0) {
        float a13 = 0.0f, a12 = 0.0f;
        #pragma unroll
        for (int w = 0; w < 8; ++w) { a13 += sh13[w]; a12 += sh12[w]; }
        float compare = 2.0f - sqrtf(a13) + sqrtf(a12);
        g_row_hinge[row] = fmaxf(0.0f, compare);
        // Fire-and-forget, release-ordered count: makes the hinge store above
        // visible to any acquire-reader of g_done. No membar, no return value.
        asm volatile("red.release.gpu.global.add.u32 [%0], 1;"
                     :: "l"(&g_done) : "memory");
    }

    // ---- Designated finisher: CTA 4095 is scheduled in the last wave. ----
    if (blockIdx.x == BATCH - 1) {
        if (threadIdx.x == 0) {
            unsigned int v;
            do {
                asm volatile("ld.acquire.gpu.global.u32 %0, [%1];"
                             : "=r"(v) : "l"(&g_done) : "memory");
                if (v >= (unsigned int)BATCH) break;
                __nanosleep(64);
            } while (true);
        }
        __syncthreads();   // extend thread0's acquire to the whole CTA

        // 4096 hinges, 256 threads -> 4 float4 each (L2-hot)
        const float4* hp = reinterpret_cast<const float4*>(g_row_hinge);
        float s = 0.0f;
        #pragma unroll
        for (int it = 0; it < BATCH / 4 / 256; ++it) {
            float4 v4 = hp[it * 256 + threadIdx.x];
            s += (v4.x + v4.y) + (v4.z + v4.w);
        }

        #pragma unroll
        for (int off = 16; off > 0; off >>= 1)
            s += __shfl_xor_sync(0xFFFFFFFFu, s, off);

        __shared__ float shf[8];
        if (lane == 0) shf[wid] = s;
        __syncthreads();

        if (threadIdx.x == 0) {
            float tot = 0.0f;
            #pragma unroll
            for (int w = 0; w < 8; ++w) tot += shf[w];
            out[0] = tot * (float)BATCH;  // [B,B] broadcast -> scale by B
            g_done = 0;                   // reset for next graph replay
        }
    }
}

extern "C" void kernel_launch(void* const* d_in, const int* in_sizes, int n_in,
                              void* d_out, int out_size)
{
    const float* out1 = (const float*)d_in[0];
    const float* out2 = (const float*)d_in[1];
    const float* out3 = (const float*)d_in[2];
    float* out = (float*)d_out;

    myloss_kernel<<<BATCH, 256>>>(out1, out2, out3, out);
}

// round 8
// speedup vs baseline: 1.1292x; 1.0110x over previous
#include <cuda_runtime.h>

#define BATCH 4096
#define FEAT  4096

// scratch (device-global; no allocation allowed in kernel_launch)
__device__ float g_row_hinge[BATCH];
__device__ unsigned int g_done;   // zero at load; reset by designated CTA each run

__global__ void __launch_bounds__(256, 8) myloss_kernel(
    const float* __restrict__ out1,
    const float* __restrict__ out2,
    const float* __restrict__ out3,
    float* __restrict__ out)
{
    const int row = blockIdx.x;
    const size_t base = (size_t)row * FEAT;
    const float4* __restrict__ p1 = reinterpret_cast<const float4*>(out1 + base);
    const float4* __restrict__ p2 = reinterpret_cast<const float4*>(out2 + base);
    const float4* __restrict__ p3 = reinterpret_cast<const float4*>(out3 + base);

    float s13 = 0.0f;  // sum (o1-o3)^2
    float s12 = 0.0f;  // sum (o1-o2)^2

    // FEAT/4 = 1024 float4 per row; 256 threads -> 4 iterations each.
    #pragma unroll
    for (int it = 0; it < (FEAT / 4) / 256; ++it) {
        const int i = it * 256 + threadIdx.x;
        float4 a = __ldcs(p1 + i);
        float4 b = __ldcs(p2 + i);
        float4 c = __ldcs(p3 + i);
        float d;
        d = a.x - c.x; s13 = fmaf(d, d, s13);
        d = a.y - c.y; s13 = fmaf(d, d, s13);
        d = a.z - c.z; s13 = fmaf(d, d, s13);
        d = a.w - c.w; s13 = fmaf(d, d, s13);
        d = a.x - b.x; s12 = fmaf(d, d, s12);
        d = a.y - b.y; s12 = fmaf(d, d, s12);
        d = a.z - b.z; s12 = fmaf(d, d, s12);
        d = a.w - b.w; s12 = fmaf(d, d, s12);
    }

    // warp reduction of both sums
    #pragma unroll
    for (int off = 16; off > 0; off >>= 1) {
        s13 += __shfl_xor_sync(0xFFFFFFFFu, s13, off);
        s12 += __shfl_xor_sync(0xFFFFFFFFu, s12, off);
    }

    __shared__ float sh13[8];
    __shared__ float sh12[8];
    const int lane = threadIdx.x & 31;
    const int wid  = threadIdx.x >> 5;
    if (lane == 0) { sh13[wid] = s13; sh12[wid] = s12; }
    __syncthreads();

    if (threadIdx.x == 0) {
        float a13 = 0.0f, a12 = 0.0f;
        #pragma unroll
        for (int w = 0; w < 8; ++w) { a13 += sh13[w]; a12 += sh12[w]; }
        float compare = 2.0f - sqrtf(a13) + sqrtf(a12);
        g_row_hinge[row] = fmaxf(0.0f, compare);
        // Fire-and-forget, release-ordered count: makes the hinge store above
        // visible to any acquire-reader of g_done. No membar, no return value.
        asm volatile("red.release.gpu.global.add.u32 [%0], 1;"
                     :: "l"(&g_done) : "memory");
    }

    // ---- Designated finisher: CTA 4095 is scheduled in the last wave. ----
    if (blockIdx.x == BATCH - 1) {
        if (threadIdx.x == 0) {
            unsigned int v;
            do {
                asm volatile("ld.acquire.gpu.global.u32 %0, [%1];"
                             : "=r"(v) : "l"(&g_done) : "memory");
                if (v >= (unsigned int)BATCH) break;
                __nanosleep(64);
            } while (true);
        }
        __syncthreads();   // extend thread0's acquire to the whole CTA

        // 4096 hinges, 256 threads -> 4 float4 each (L2-hot)
        const float4* hp = reinterpret_cast<const float4*>(g_row_hinge);
        float s = 0.0f;
        #pragma unroll
        for (int it = 0; it < BATCH / 4 / 256; ++it) {
            float4 v4 = hp[it * 256 + threadIdx.x];
            s += (v4.x + v4.y) + (v4.z + v4.w);
        }

        #pragma unroll
        for (int off = 16; off > 0; off >>= 1)
            s += __shfl_xor_sync(0xFFFFFFFFu, s, off);

        __shared__ float shf[8];
        if (lane == 0) shf[wid] = s;
        __syncthreads();

        if (threadIdx.x == 0) {
            float tot = 0.0f;
            #pragma unroll
            for (int w = 0; w < 8; ++w) tot += shf[w];
            out[0] = tot * (float)BATCH;  // [B,B] broadcast -> scale by B
            g_done = 0;                   // reset for next graph replay
        }
    }
}

extern "C" void kernel_launch(void* const* d_in, const int* in_sizes, int n_in,
                              void* d_out, int out_size)
{
    const float* out1 = (const float*)d_in[0];
    const float* out2 = (const float*)d_in[1];
    const float* out3 = (const float*)d_in[2];
    float* out = (float*)d_out;

    myloss_kernel<<<BATCH, 256>>>(out1, out2, out3, out);
}

// round 9
// speedup vs baseline: 1.1324x; 1.0028x over previous
#include <cuda_runtime.h>

#define BATCH 4096
#define FEAT  4096
#define TPB   512

// scratch (device-global; no allocation allowed in kernel_launch)
__device__ float g_row_hinge[BATCH];
__device__ unsigned int g_done;   // zero at load; reset by designated CTA each run

__global__ void __launch_bounds__(TPB, 4) myloss_kernel(
    const float* __restrict__ out1,
    const float* __restrict__ out2,
    const float* __restrict__ out3,
    float* __restrict__ out)
{
    const int row = blockIdx.x;
    const size_t base = (size_t)row * FEAT;
    const float4* __restrict__ p1 = reinterpret_cast<const float4*>(out1 + base);
    const float4* __restrict__ p2 = reinterpret_cast<const float4*>(out2 + base);
    const float4* __restrict__ p3 = reinterpret_cast<const float4*>(out3 + base);

    float s13 = 0.0f;  // sum (o1-o3)^2
    float s12 = 0.0f;  // sum (o1-o2)^2

    // FEAT/4 = 1024 float4 per row; 512 threads -> 2 iterations each.
    #pragma unroll
    for (int it = 0; it < (FEAT / 4) / TPB; ++it) {
        const int i = it * TPB + threadIdx.x;
        float4 a = __ldcs(p1 + i);
        float4 b = __ldcs(p2 + i);
        float4 c = __ldcs(p3 + i);
        float d;
        d = a.x - c.x; s13 = fmaf(d, d, s13);
        d = a.y - c.y; s13 = fmaf(d, d, s13);
        d = a.z - c.z; s13 = fmaf(d, d, s13);
        d = a.w - c.w; s13 = fmaf(d, d, s13);
        d = a.x - b.x; s12 = fmaf(d, d, s12);
        d = a.y - b.y; s12 = fmaf(d, d, s12);
        d = a.z - b.z; s12 = fmaf(d, d, s12);
        d = a.w - b.w; s12 = fmaf(d, d, s12);
    }

    // warp reduction of both sums
    #pragma unroll
    for (int off = 16; off > 0; off >>= 1) {
        s13 += __shfl_xor_sync(0xFFFFFFFFu, s13, off);
        s12 += __shfl_xor_sync(0xFFFFFFFFu, s12, off);
    }

    __shared__ float sh13[TPB / 32];
    __shared__ float sh12[TPB / 32];
    const int lane = threadIdx.x & 31;
    const int wid  = threadIdx.x >> 5;
    if (lane == 0) { sh13[wid] = s13; sh12[wid] = s12; }
    __syncthreads();

    if (threadIdx.x == 0) {
        float a13 = 0.0f, a12 = 0.0f;
        #pragma unroll
        for (int w = 0; w < TPB / 32; ++w) { a13 += sh13[w]; a12 += sh12[w]; }
        float compare = 2.0f - sqrtf(a13) + sqrtf(a12);
        g_row_hinge[row] = fmaxf(0.0f, compare);
        // Fire-and-forget, release-ordered count: makes the hinge store above
        // visible to any acquire-reader of g_done. No membar, no return value.
        asm volatile("red.release.gpu.global.add.u32 [%0], 1;"
                     :: "l"(&g_done) : "memory");
    }

    // ---- Designated finisher: CTA 4095 is scheduled in the last wave. ----
    if (blockIdx.x == BATCH - 1) {
        if (threadIdx.x == 0) {
            unsigned int v;
            do {
                asm volatile("ld.acquire.gpu.global.u32 %0, [%1];"
                             : "=r"(v) : "l"(&g_done) : "memory");
                if (v >= (unsigned int)BATCH) break;
                __nanosleep(64);
            } while (true);
        }
        __syncthreads();   // extend thread0's acquire to the whole CTA

        // 4096 hinges, 512 threads -> 2 float4 each (L2-hot)
        const float4* hp = reinterpret_cast<const float4*>(g_row_hinge);
        float s = 0.0f;
        #pragma unroll
        for (int it = 0; it < BATCH / 4 / TPB; ++it) {
            float4 v4 = hp[it * TPB + threadIdx.x];
            s += (v4.x + v4.y) + (v4.z + v4.w);
        }

        #pragma unroll
        for (int off = 16; off > 0; off >>= 1)
            s += __shfl_xor_sync(0xFFFFFFFFu, s, off);

        __shared__ float shf[TPB / 32];
        if (lane == 0) shf[wid] = s;
        __syncthreads();

        if (threadIdx.x == 0) {
            float tot = 0.0f;
            #pragma unroll
            for (int w = 0; w < TPB / 32; ++w) tot += shf[w];
            out[0] = tot * (float)BATCH;  // [B,B] broadcast -> scale by B
            g_done = 0;                   // reset for next graph replay
        }
    }
}

extern "C" void kernel_launch(void* const* d_in, const int* in_sizes, int n_in,
                              void* d_out, int out_size)
{
    const float* out1 = (const float*)d_in[0];
    const float* out2 = (const float*)d_in[1];
    const float* out3 = (const float*)d_in[2];
    float* out = (float*)d_out;

    myloss_kernel<<<BATCH, TPB>>>(out1, out2, out3, out);
}